// round 3
// baseline (speedup 1.0000x reference)
#include <cuda_runtime.h>
#include <cuda_bf16.h>
#include <math.h>

// Shapes: B=2, G=8 -> BG=16 ; N=4096 ; D=1024. kv_len==1 collapses attention:
//   v[bg]  = guidance[bg] @ Wv^T + bv          (Wv = in_proj_w rows [2048:3072])
//   o[bg]  = v[bg] @ Wout^T + bo               (constant across sequence)
//   y[row] = rmsnorm(x[row] + o[bg], norm_w)
#define BG   16
#define NSEQ 4096
#define DIM  1024
#define NROWS (BG * NSEQ)
#define EPSF 1e-6f

__device__ float g_v[BG * DIM];
__device__ float g_o[BG * DIM];

// ---------------------------------------------------------------------------
// GEMV, W-deduplicated: one warp per output column i (1024 warps total).
// Each warp streams W row i ONCE and accumulates against all BG=16 A-rows
// (A = 64KB, L1/L2 resident). W traffic: 4MB instead of 64MB.
// ---------------------------------------------------------------------------
__global__ void __launch_bounds__(256)
gemv_allbg_kernel(const float* __restrict__ A,     // [BG, DIM]
                  const float* __restrict__ W,     // [DIM, DIM] row-major
                  const float* __restrict__ bias,  // [DIM]
                  float* __restrict__ out)         // [BG, DIM]
{
    const int i    = (blockIdx.x * blockDim.x + threadIdx.x) >> 5;  // output col
    const int lane = threadIdx.x & 31;
    if (i >= DIM) return;

    const float* __restrict__ w = W + (size_t)i * DIM;

    float acc[BG];
    #pragma unroll
    for (int b = 0; b < BG; b++) acc[b] = 0.0f;

    // 1024 elems / 32 lanes = 8 float4 chunks per lane
    #pragma unroll
    for (int d = lane * 4; d < DIM; d += 32 * 4) {
        const float4 wv = *reinterpret_cast<const float4*>(w + d);
        #pragma unroll
        for (int b = 0; b < BG; b++) {
            const float4 av = *reinterpret_cast<const float4*>(A + b * DIM + d);
            acc[b] = fmaf(av.x, wv.x, acc[b]);
            acc[b] = fmaf(av.y, wv.y, acc[b]);
            acc[b] = fmaf(av.z, wv.z, acc[b]);
            acc[b] = fmaf(av.w, wv.w, acc[b]);
        }
    }

    const float bi = bias[i];
    #pragma unroll
    for (int b = 0; b < BG; b++) {
        float s = acc[b];
        #pragma unroll
        for (int off = 16; off > 0; off >>= 1)
            s += __shfl_xor_sync(0xffffffffu, s, off);
        if (lane == 0) out[b * DIM + i] = s + bi;
    }
}

// ---------------------------------------------------------------------------
// Fused residual-add + RMSNorm. One 256-thread block per row, float4/thread.
// x/y are pure streams -> __ldcs/__stcs (evict-first, keep o + norm_w hot in L2).
// ---------------------------------------------------------------------------
__global__ void __launch_bounds__(256)
fused_add_rmsnorm_kernel(const float* __restrict__ x,   // [NROWS, DIM]
                         const float* __restrict__ o,   // [BG, DIM]
                         const float* __restrict__ w,   // [DIM]
                         float* __restrict__ y)         // [NROWS, DIM]
{
    const int row = blockIdx.x;
    const int bg  = row >> 12;               // row / NSEQ
    const int t   = threadIdx.x;
    const size_t base = (size_t)row * DIM + t * 4;

    const float4 x4 = __ldcs(reinterpret_cast<const float4*>(x + base));
    const float4 o4 = *reinterpret_cast<const float4*>(o + bg * DIM + t * 4);

    float4 s;
    s.x = x4.x + o4.x;
    s.y = x4.y + o4.y;
    s.z = x4.z + o4.z;
    s.w = x4.w + o4.w;

    float ss = s.x * s.x + s.y * s.y + s.z * s.z + s.w * s.w;

    #pragma unroll
    for (int off = 16; off > 0; off >>= 1)
        ss += __shfl_xor_sync(0xffffffffu, ss, off);

    __shared__ float red[8];
    __shared__ float inv_s;
    const int lane = t & 31;
    const int wid  = t >> 5;
    if (lane == 0) red[wid] = ss;
    __syncthreads();
    if (wid == 0) {
        float v = (lane < 8) ? red[lane] : 0.0f;
        #pragma unroll
        for (int off = 4; off > 0; off >>= 1)
            v += __shfl_xor_sync(0xffffffffu, v, off);
        if (lane == 0)
            inv_s = rsqrtf(v * (1.0f / (float)DIM) + EPSF);
    }
    __syncthreads();
    const float inv = inv_s;

    const float4 w4 = *reinterpret_cast<const float4*>(w + t * 4);
    float4 r;
    r.x = s.x * inv * w4.x;
    r.y = s.y * inv * w4.y;
    r.z = s.z * inv * w4.z;
    r.w = s.w * inv * w4.w;
    __stcs(reinterpret_cast<float4*>(y + base), r);
}

// ---------------------------------------------------------------------------
// Inputs (metadata order):
//  0: x [2,8,4096,1024]  1: guidance [2,8,1024]  2: in_proj_w [3072,1024]
//  3: in_proj_b [3072]   4: out_proj_w [1024,1024] 5: out_proj_b [1024]
//  6: norm_w [1024]      out: y [2,8,4096,1024] f32
// ---------------------------------------------------------------------------
extern "C" void kernel_launch(void* const* d_in, const int* in_sizes, int n_in,
                              void* d_out, int out_size)
{
    const float* x        = (const float*)d_in[0];
    const float* guidance = (const float*)d_in[1];
    const float* in_w     = (const float*)d_in[2];
    const float* in_b     = (const float*)d_in[3];
    const float* out_w    = (const float*)d_in[4];
    const float* out_b    = (const float*)d_in[5];
    const float* norm_w   = (const float*)d_in[6];
    float* y = (float*)d_out;

    float* v_scratch;
    float* o_scratch;
    cudaGetSymbolAddress((void**)&v_scratch, g_v);
    cudaGetSymbolAddress((void**)&o_scratch, g_o);

    const float* Wv = in_w + (size_t)2 * DIM * DIM;
    const float* bv = in_b + 2 * DIM;

    // 1024 warps -> 128 blocks of 256 threads (8 warps each)
    const int gemv_blocks = DIM / 8;
    gemv_allbg_kernel<<<gemv_blocks, 256>>>(guidance, Wv, bv, v_scratch);
    gemv_allbg_kernel<<<gemv_blocks, 256>>>(v_scratch, out_w, out_b, o_scratch);

    fused_add_rmsnorm_kernel<<<NROWS, 256>>>(x, o_scratch, norm_w, y);
}

// round 4
// speedup vs baseline: 1.0161x; 1.0161x over previous
#include <cuda_runtime.h>
#include <cuda_bf16.h>
#include <math.h>

// Shapes: B=2, G=8 -> BG=16 ; N=4096 ; D=1024. kv_len==1 collapses attention:
//   v[bg]  = guidance[bg] @ Wv^T + bv          (Wv = in_proj_w rows [2048:3072])
//   o[bg]  = v[bg] @ Wout^T + bo               (constant across sequence)
//   y[row] = rmsnorm(x[row] + o[bg], norm_w)
#define BG   16
#define NSEQ 4096
#define DIM  1024
#define NROWS (BG * NSEQ)
#define EPSF 1e-6f

__device__ float g_v[BG * DIM];
__device__ float g_o[BG * DIM];

// ---------------------------------------------------------------------------
// GEMV, W-deduplicated: one warp per output column i (1024 warps total).
// Each warp streams W row i ONCE and accumulates against all BG=16 A-rows
// (A = 64KB, L1/L2 resident). W traffic: 4MB instead of 64MB.
// ---------------------------------------------------------------------------
__global__ void __launch_bounds__(256)
gemv_allbg_kernel(const float* __restrict__ A,     // [BG, DIM]
                  const float* __restrict__ W,     // [DIM, DIM] row-major
                  const float* __restrict__ bias,  // [DIM]
                  float* __restrict__ out)         // [BG, DIM]
{
    const int i    = (blockIdx.x * blockDim.x + threadIdx.x) >> 5;  // output col
    const int lane = threadIdx.x & 31;
    if (i >= DIM) return;

    const float* __restrict__ w = W + (size_t)i * DIM;

    float acc[BG];
    #pragma unroll
    for (int b = 0; b < BG; b++) acc[b] = 0.0f;

    // 1024 elems / 32 lanes = 8 float4 chunks per lane
    #pragma unroll
    for (int d = lane * 4; d < DIM; d += 32 * 4) {
        const float4 wv = *reinterpret_cast<const float4*>(w + d);
        #pragma unroll
        for (int b = 0; b < BG; b++) {
            const float4 av = *reinterpret_cast<const float4*>(A + b * DIM + d);
            acc[b] = fmaf(av.x, wv.x, acc[b]);
            acc[b] = fmaf(av.y, wv.y, acc[b]);
            acc[b] = fmaf(av.z, wv.z, acc[b]);
            acc[b] = fmaf(av.w, wv.w, acc[b]);
        }
    }

    const float bi = bias[i];
    #pragma unroll
    for (int b = 0; b < BG; b++) {
        float s = acc[b];
        #pragma unroll
        for (int off = 16; off > 0; off >>= 1)
            s += __shfl_xor_sync(0xffffffffu, s, off);
        if (lane == 0) out[b * DIM + i] = s + bi;
    }
}

// ---------------------------------------------------------------------------
// Fused residual-add + RMSNorm. One 256-thread block per row, float4/thread.
// x/y are pure streams -> __ldcs/__stcs (evict-first, keep o + norm_w hot in L2).
// ---------------------------------------------------------------------------
__global__ void __launch_bounds__(256)
fused_add_rmsnorm_kernel(const float* __restrict__ x,   // [NROWS, DIM]
                         const float* __restrict__ o,   // [BG, DIM]
                         const float* __restrict__ w,   // [DIM]
                         float* __restrict__ y)         // [NROWS, DIM]
{
    const int row = blockIdx.x;
    const int bg  = row >> 12;               // row / NSEQ
    const int t   = threadIdx.x;
    const size_t base = (size_t)row * DIM + t * 4;

    const float4 x4 = __ldcs(reinterpret_cast<const float4*>(x + base));
    const float4 o4 = *reinterpret_cast<const float4*>(o + bg * DIM + t * 4);

    float4 s;
    s.x = x4.x + o4.x;
    s.y = x4.y + o4.y;
    s.z = x4.z + o4.z;
    s.w = x4.w + o4.w;

    float ss = s.x * s.x + s.y * s.y + s.z * s.z + s.w * s.w;

    #pragma unroll
    for (int off = 16; off > 0; off >>= 1)
        ss += __shfl_xor_sync(0xffffffffu, ss, off);

    __shared__ float red[8];
    __shared__ float inv_s;
    const int lane = t & 31;
    const int wid  = t >> 5;
    if (lane == 0) red[wid] = ss;
    __syncthreads();
    if (wid == 0) {
        float v = (lane < 8) ? red[lane] : 0.0f;
        #pragma unroll
        for (int off = 4; off > 0; off >>= 1)
            v += __shfl_xor_sync(0xffffffffu, v, off);
        if (lane == 0)
            inv_s = rsqrtf(v * (1.0f / (float)DIM) + EPSF);
    }
    __syncthreads();
    const float inv = inv_s;

    const float4 w4 = *reinterpret_cast<const float4*>(w + t * 4);
    float4 r;
    r.x = s.x * inv * w4.x;
    r.y = s.y * inv * w4.y;
    r.z = s.z * inv * w4.z;
    r.w = s.w * inv * w4.w;
    __stcs(reinterpret_cast<float4*>(y + base), r);
}

// ---------------------------------------------------------------------------
// Inputs (metadata order):
//  0: x [2,8,4096,1024]  1: guidance [2,8,1024]  2: in_proj_w [3072,1024]
//  3: in_proj_b [3072]   4: out_proj_w [1024,1024] 5: out_proj_b [1024]
//  6: norm_w [1024]      out: y [2,8,4096,1024] f32
// ---------------------------------------------------------------------------
extern "C" void kernel_launch(void* const* d_in, const int* in_sizes, int n_in,
                              void* d_out, int out_size)
{
    const float* x        = (const float*)d_in[0];
    const float* guidance = (const float*)d_in[1];
    const float* in_w     = (const float*)d_in[2];
    const float* in_b     = (const float*)d_in[3];
    const float* out_w    = (const float*)d_in[4];
    const float* out_b    = (const float*)d_in[5];
    const float* norm_w   = (const float*)d_in[6];
    float* y = (float*)d_out;

    float* v_scratch;
    float* o_scratch;
    cudaGetSymbolAddress((void**)&v_scratch, g_v);
    cudaGetSymbolAddress((void**)&o_scratch, g_o);

    const float* Wv = in_w + (size_t)2 * DIM * DIM;
    const float* bv = in_b + 2 * DIM;

    // 1024 warps -> 128 blocks of 256 threads (8 warps each)
    const int gemv_blocks = DIM / 8;
    gemv_allbg_kernel<<<gemv_blocks, 256>>>(guidance, Wv, bv, v_scratch);
    gemv_allbg_kernel<<<gemv_blocks, 256>>>(v_scratch, out_w, out_b, o_scratch);

    fused_add_rmsnorm_kernel<<<NROWS, 256>>>(x, o_scratch, norm_w, y);
}

// round 5
// speedup vs baseline: 1.0191x; 1.0029x over previous
#include <cuda_runtime.h>
#include <cuda_bf16.h>
#include <math.h>

// Shapes: B=2, G=8 -> BG=16 ; N=4096 ; D=1024. kv_len==1 collapses attention:
//   v[bg]  = guidance[bg] @ Wv^T + bv          (Wv = in_proj_w rows [2048:3072])
//   o[bg]  = v[bg] @ Wout^T + bo               (constant across sequence)
//   y[row] = rmsnorm(x[row] + o[bg], norm_w)
#define BG   16
#define NSEQ 4096
#define DIM  1024
#define NROWS (BG * NSEQ)
#define EPSF 1e-6f

__device__ float g_v[BG * DIM];
__device__ float g_o[BG * DIM];

// ---------------------------------------------------------------------------
// GEMV, W-deduplicated: one warp per output column i (1024 warps total).
// Each warp streams W row i ONCE and accumulates against all BG=16 A-rows
// (A = 64KB, L1/L2 resident). W traffic: 4MB instead of 64MB.
// ---------------------------------------------------------------------------
__global__ void __launch_bounds__(256)
gemv_allbg_kernel(const float* __restrict__ A,     // [BG, DIM]
                  const float* __restrict__ W,     // [DIM, DIM] row-major
                  const float* __restrict__ bias,  // [DIM]
                  float* __restrict__ out)         // [BG, DIM]
{
    const int i    = (blockIdx.x * blockDim.x + threadIdx.x) >> 5;  // output col
    const int lane = threadIdx.x & 31;
    if (i >= DIM) return;

    const float* __restrict__ w = W + (size_t)i * DIM;

    float acc[BG];
    #pragma unroll
    for (int b = 0; b < BG; b++) acc[b] = 0.0f;

    // 1024 elems / 32 lanes = 8 float4 chunks per lane
    #pragma unroll
    for (int d = lane * 4; d < DIM; d += 32 * 4) {
        const float4 wv = *reinterpret_cast<const float4*>(w + d);
        #pragma unroll
        for (int b = 0; b < BG; b++) {
            const float4 av = *reinterpret_cast<const float4*>(A + b * DIM + d);
            acc[b] = fmaf(av.x, wv.x, acc[b]);
            acc[b] = fmaf(av.y, wv.y, acc[b]);
            acc[b] = fmaf(av.z, wv.z, acc[b]);
            acc[b] = fmaf(av.w, wv.w, acc[b]);
        }
    }

    const float bi = bias[i];
    #pragma unroll
    for (int b = 0; b < BG; b++) {
        float s = acc[b];
        #pragma unroll
        for (int off = 16; off > 0; off >>= 1)
            s += __shfl_xor_sync(0xffffffffu, s, off);
        if (lane == 0) out[b * DIM + i] = s + bi;
    }
}

// ---------------------------------------------------------------------------
// Fused residual-add + RMSNorm. One 256-thread block per row, float4/thread.
// x/y are pure streams -> __ldcs/__stcs (evict-first, keep o + norm_w hot in L2).
// ---------------------------------------------------------------------------
__global__ void __launch_bounds__(256)
fused_add_rmsnorm_kernel(const float* __restrict__ x,   // [NROWS, DIM]
                         const float* __restrict__ o,   // [BG, DIM]
                         const float* __restrict__ w,   // [DIM]
                         float* __restrict__ y)         // [NROWS, DIM]
{
    const int row = blockIdx.x;
    const int bg  = row >> 12;               // row / NSEQ
    const int t   = threadIdx.x;
    const size_t base = (size_t)row * DIM + t * 4;

    const float4 x4 = __ldcs(reinterpret_cast<const float4*>(x + base));
    const float4 o4 = *reinterpret_cast<const float4*>(o + bg * DIM + t * 4);

    float4 s;
    s.x = x4.x + o4.x;
    s.y = x4.y + o4.y;
    s.z = x4.z + o4.z;
    s.w = x4.w + o4.w;

    float ss = s.x * s.x + s.y * s.y + s.z * s.z + s.w * s.w;

    #pragma unroll
    for (int off = 16; off > 0; off >>= 1)
        ss += __shfl_xor_sync(0xffffffffu, ss, off);

    __shared__ float red[8];
    __shared__ float inv_s;
    const int lane = t & 31;
    const int wid  = t >> 5;
    if (lane == 0) red[wid] = ss;
    __syncthreads();
    if (wid == 0) {
        float v = (lane < 8) ? red[lane] : 0.0f;
        #pragma unroll
        for (int off = 4; off > 0; off >>= 1)
            v += __shfl_xor_sync(0xffffffffu, v, off);
        if (lane == 0)
            inv_s = rsqrtf(v * (1.0f / (float)DIM) + EPSF);
    }
    __syncthreads();
    const float inv = inv_s;

    const float4 w4 = *reinterpret_cast<const float4*>(w + t * 4);
    float4 r;
    r.x = s.x * inv * w4.x;
    r.y = s.y * inv * w4.y;
    r.z = s.z * inv * w4.z;
    r.w = s.w * inv * w4.w;
    __stcs(reinterpret_cast<float4*>(y + base), r);
}

// ---------------------------------------------------------------------------
// Inputs (metadata order):
//  0: x [2,8,4096,1024]  1: guidance [2,8,1024]  2: in_proj_w [3072,1024]
//  3: in_proj_b [3072]   4: out_proj_w [1024,1024] 5: out_proj_b [1024]
//  6: norm_w [1024]      out: y [2,8,4096,1024] f32
// ---------------------------------------------------------------------------
extern "C" void kernel_launch(void* const* d_in, const int* in_sizes, int n_in,
                              void* d_out, int out_size)
{
    const float* x        = (const float*)d_in[0];
    const float* guidance = (const float*)d_in[1];
    const float* in_w     = (const float*)d_in[2];
    const float* in_b     = (const float*)d_in[3];
    const float* out_w    = (const float*)d_in[4];
    const float* out_b    = (const float*)d_in[5];
    const float* norm_w   = (const float*)d_in[6];
    float* y = (float*)d_out;

    float* v_scratch;
    float* o_scratch;
    cudaGetSymbolAddress((void**)&v_scratch, g_v);
    cudaGetSymbolAddress((void**)&o_scratch, g_o);

    const float* Wv = in_w + (size_t)2 * DIM * DIM;
    const float* bv = in_b + 2 * DIM;

    // 1024 warps -> 128 blocks of 256 threads (8 warps each)
    const int gemv_blocks = DIM / 8;
    gemv_allbg_kernel<<<gemv_blocks, 256>>>(guidance, Wv, bv, v_scratch);
    gemv_allbg_kernel<<<gemv_blocks, 256>>>(v_scratch, out_w, out_b, o_scratch);

    fused_add_rmsnorm_kernel<<<NROWS, 256>>>(x, o_scratch, norm_w, y);
}

// round 6
// speedup vs baseline: 1.0464x; 1.0268x over previous
#include <cuda_runtime.h>
#include <cuda_bf16.h>
#include <math.h>

// Shapes: B=2, G=8 -> BG=16 ; N=4096 ; D=1024. kv_len==1 collapses attention:
//   v[bg]  = guidance[bg] @ Wv^T + bv          (Wv = in_proj_w rows [2048:3072])
//   o[bg]  = v[bg] @ Wout^T + bo               (constant across sequence)
//   y[row] = rmsnorm(x[row] + o[bg], norm_w)
#define BG   16
#define NSEQ 4096
#define DIM  1024
#define NROWS (BG * NSEQ)
#define EPSF 1e-6f

__device__ float g_v[BG * DIM];
__device__ float g_o[BG * DIM];

// ---------------------------------------------------------------------------
// GEMV split-K: one 256-thread BLOCK per output column i (1024 blocks).
// Thread t owns W[i, 4t..4t+3] (single LDG.128, coalesced, W read once = 4MB),
// accumulates against all BG=16 A-rows (64KB, L1/L2 resident).
// Reduction: warp shfl -> smem[8][16] -> 8-lane shfl groups.
// 262K threads vs R5's 32K -> latency fully hidden.
// ---------------------------------------------------------------------------
__global__ void __launch_bounds__(256)
gemv_col_kernel(const float* __restrict__ A,     // [BG, DIM]
                const float* __restrict__ W,     // [DIM, DIM] row-major
                const float* __restrict__ bias,  // [DIM]
                float* __restrict__ out)         // [BG, DIM]
{
    const int i = blockIdx.x;                // output column
    const int t = threadIdx.x;               // 0..255

    const float4 w4 = *reinterpret_cast<const float4*>(W + (size_t)i * DIM + t * 4);

    float p[BG];
    #pragma unroll
    for (int b = 0; b < BG; b++) {
        const float4 a4 = *reinterpret_cast<const float4*>(A + b * DIM + t * 4);
        p[b] = w4.x * a4.x + w4.y * a4.y + w4.z * a4.z + w4.w * a4.w;
    }

    // warp-level reduce for each of the 16 partials
    #pragma unroll
    for (int b = 0; b < BG; b++) {
        #pragma unroll
        for (int off = 16; off > 0; off >>= 1)
            p[b] += __shfl_xor_sync(0xffffffffu, p[b], off);
    }

    __shared__ float red[8][BG];
    const int lane = t & 31;
    const int wid  = t >> 5;
    if (lane == 0) {
        #pragma unroll
        for (int b = 0; b < BG; b++) red[wid][b] = p[b];
    }
    __syncthreads();

    // 128 values (8 warps x 16 batches): thread t<128 -> batch t>>3, partial t&7
    if (t < 128) {
        const int b = t >> 3;
        const int j = t & 7;
        float v = red[j][b];
        #pragma unroll
        for (int off = 4; off > 0; off >>= 1)
            v += __shfl_xor_sync(0xffffffffu, v, off);
        if (j == 0) out[b * DIM + i] = v + bias[i];
    }
}

// ---------------------------------------------------------------------------
// Fused residual-add + RMSNorm. One 256-thread block per row, float4/thread.
// x/y are pure streams -> __ldcs/__stcs (evict-first; o + norm_w stay hot).
// ---------------------------------------------------------------------------
__global__ void __launch_bounds__(256)
fused_add_rmsnorm_kernel(const float* __restrict__ x,   // [NROWS, DIM]
                         const float* __restrict__ o,   // [BG, DIM]
                         const float* __restrict__ w,   // [DIM]
                         float* __restrict__ y)         // [NROWS, DIM]
{
    const int row = blockIdx.x;
    const int bg  = row >> 12;               // row / NSEQ
    const int t   = threadIdx.x;
    const size_t base = (size_t)row * DIM + t * 4;

    const float4 x4 = __ldcs(reinterpret_cast<const float4*>(x + base));
    const float4 o4 = *reinterpret_cast<const float4*>(o + bg * DIM + t * 4);

    float4 s;
    s.x = x4.x + o4.x;
    s.y = x4.y + o4.y;
    s.z = x4.z + o4.z;
    s.w = x4.w + o4.w;

    float ss = s.x * s.x + s.y * s.y + s.z * s.z + s.w * s.w;

    #pragma unroll
    for (int off = 16; off > 0; off >>= 1)
        ss += __shfl_xor_sync(0xffffffffu, ss, off);

    __shared__ float red[8];
    __shared__ float inv_s;
    const int lane = t & 31;
    const int wid  = t >> 5;
    if (lane == 0) red[wid] = ss;
    __syncthreads();
    if (wid == 0) {
        float v = (lane < 8) ? red[lane] : 0.0f;
        #pragma unroll
        for (int off = 4; off > 0; off >>= 1)
            v += __shfl_xor_sync(0xffffffffu, v, off);
        if (lane == 0)
            inv_s = rsqrtf(v * (1.0f / (float)DIM) + EPSF);
    }
    __syncthreads();
    const float inv = inv_s;

    const float4 w4 = *reinterpret_cast<const float4*>(w + t * 4);
    float4 r;
    r.x = s.x * inv * w4.x;
    r.y = s.y * inv * w4.y;
    r.z = s.z * inv * w4.z;
    r.w = s.w * inv * w4.w;
    __stcs(reinterpret_cast<float4*>(y + base), r);
}

// ---------------------------------------------------------------------------
// Inputs (metadata order):
//  0: x [2,8,4096,1024]  1: guidance [2,8,1024]  2: in_proj_w [3072,1024]
//  3: in_proj_b [3072]   4: out_proj_w [1024,1024] 5: out_proj_b [1024]
//  6: norm_w [1024]      out: y [2,8,4096,1024] f32
// ---------------------------------------------------------------------------
extern "C" void kernel_launch(void* const* d_in, const int* in_sizes, int n_in,
                              void* d_out, int out_size)
{
    const float* x        = (const float*)d_in[0];
    const float* guidance = (const float*)d_in[1];
    const float* in_w     = (const float*)d_in[2];
    const float* in_b     = (const float*)d_in[3];
    const float* out_w    = (const float*)d_in[4];
    const float* out_b    = (const float*)d_in[5];
    const float* norm_w   = (const float*)d_in[6];
    float* y = (float*)d_out;

    float* v_scratch;
    float* o_scratch;
    cudaGetSymbolAddress((void**)&v_scratch, g_v);
    cudaGetSymbolAddress((void**)&o_scratch, g_o);

    const float* Wv = in_w + (size_t)2 * DIM * DIM;
    const float* bv = in_b + 2 * DIM;

    gemv_col_kernel<<<DIM, 256>>>(guidance, Wv, bv, v_scratch);
    gemv_col_kernel<<<DIM, 256>>>(v_scratch, out_w, out_b, o_scratch);

    fused_add_rmsnorm_kernel<<<NROWS, 256>>>(x, o_scratch, norm_w, y);
}